// round 15
// baseline (speedup 1.0000x reference)
#include <cuda_runtime.h>
#include <cuda_fp16.h>
#include <cstdint>

#define NT 256
#define BTOT 16384

// ---- dynamic smem layout (BYTE offsets) ----
#define B_ACT   0          // half [128][136]  (272B/row, ==16 mod 128)
#define B_W1    34816      // half [128][136]
#define B_WUL   69632      // half [64][72]    (144B/row, ==16 mod 128)
#define B_W2    78848      // half [128][72]
#define B_PING  97280      // half [128][72]
#define B_HEAD  115712     // float [128][68]  (272B/row)
#define B_WV    150528     // float[256]
#define B_BUL   151552     // float[64]
#define B_B1    151808     // float[128]
#define B_B2    152320     // float[64]
#define B_W3    152576     // float[64]
#define B_OUT   152832     // float[128]
#define SMEM_BYTES 153344

__device__ __forceinline__ uint32_t smem_u32(const void* p) {
    uint32_t a;
    asm("{ .reg .u64 t; cvta.to.shared.u64 t, %1; cvt.u32.u64 %0, t; }" : "=r"(a) : "l"(p));
    return a;
}
__device__ __forceinline__ uint32_t pk(float a, float b) {
    __half2 h = __floats2half2_rn(a, b);
    return *(uint32_t*)&h;
}
__device__ __forceinline__ float2 up(uint32_t u) {
    return __half22float2(*(__half2*)&u);
}
__device__ __forceinline__ void ldsm4(uint32_t* r, uint32_t addr) {
    asm volatile("ldmatrix.sync.aligned.m8n8.x4.shared.b16 {%0,%1,%2,%3}, [%4];"
                 : "=r"(r[0]), "=r"(r[1]), "=r"(r[2]), "=r"(r[3]) : "r"(addr));
}
__device__ __forceinline__ void ldsm4t(uint32_t* r, uint32_t addr) {
    asm volatile("ldmatrix.sync.aligned.m8n8.x4.trans.shared.b16 {%0,%1,%2,%3}, [%4];"
                 : "=r"(r[0]), "=r"(r[1]), "=r"(r[2]), "=r"(r[3]) : "r"(addr));
}
__device__ __forceinline__ void mma16(float* c, const uint32_t* a, const uint32_t* b) {
    asm("mma.sync.aligned.m16n8k16.row.col.f32.f16.f16.f32 "
        "{%0,%1,%2,%3},{%4,%5,%6,%7},{%8,%9},{%0,%1,%2,%3};"
        : "+f"(c[0]), "+f"(c[1]), "+f"(c[2]), "+f"(c[3])
        : "r"(a[0]), "r"(a[1]), "r"(a[2]), "r"(a[3]), "r"(b[0]), "r"(b[1]));
}
__device__ __forceinline__ void cpa16(uint32_t dst, const void* src) {
    asm volatile("cp.async.cg.shared.global [%0], [%1], 16;" :: "r"(dst), "l"(src));
}
__device__ __forceinline__ void cpa4(uint32_t dst, const void* src) {
    asm volatile("cp.async.ca.shared.global [%0], [%1], 4;" :: "r"(dst), "l"(src));
}
#define CP_COMMIT() asm volatile("cp.async.commit_group;" ::: "memory")
#define CP_WAIT(n)  asm volatile("cp.async.wait_group %0;" :: "n"(n) : "memory")
#define BAR_U() asm volatile("bar.sync 1, 128;" ::: "memory")
#define BAR_C() asm volatile("bar.sync 2, 128;" ::: "memory")
#define BAR_G(g) asm volatile("bar.sync %0, 128;" :: "r"((g) + 1) : "memory")

__global__ __launch_bounds__(NT, 1)
void multikr_mma_kernel(const int* __restrict__ user_id,
                        const int* __restrict__ item_id,
                        const float* __restrict__ rec_target,
                        const float* __restrict__ user_emb,
                        const float* __restrict__ item_emb,
                        const float* __restrict__ entity_emb,
                        const float* __restrict__ w_vv,
                        const float* __restrict__ w_ev,
                        const float* __restrict__ w_ve,
                        const float* __restrict__ w_ee,
                        const float* __restrict__ b_v,
                        const float* __restrict__ b_e,
                        const float* __restrict__ Wul,
                        const float* __restrict__ bul,
                        const float* __restrict__ W1,
                        const float* __restrict__ b1,
                        const float* __restrict__ W2,
                        const float* __restrict__ b2,
                        const float* __restrict__ W3,
                        const float* __restrict__ b3,
                        float* __restrict__ out,
                        int out_size)
{
    extern __shared__ char smem[];
    __half* sActH  = (__half*)(smem + B_ACT);
    __half* sW1H   = (__half*)(smem + B_W1);
    __half* sWulH  = (__half*)(smem + B_WUL);
    __half* sW2H   = (__half*)(smem + B_W2);
    __half* sPingH = (__half*)(smem + B_PING);
    float*  sHead  = (float*)(smem + B_HEAD);
    float*  sWV    = (float*)(smem + B_WV);
    float*  sBUL   = (float*)(smem + B_BUL);
    float*  sB1    = (float*)(smem + B_B1);
    float*  sB2    = (float*)(smem + B_B2);
    float*  sW3    = (float*)(smem + B_W3);
    float*  sOut   = (float*)(smem + B_OUT);

    const int t    = threadIdx.x;
    const int l    = t & 31;
    const int wid  = t >> 5;
    const int mtx  = l >> 3, p = l & 7;
    const int base = blockIdx.x * 128;

    const uint32_t uAct  = smem_u32(sActH);
    const uint32_t uW1s  = smem_u32(sW1H);
    const uint32_t uWuls = smem_u32(sWulH);
    const uint32_t uW2s  = smem_u32(sW2H);
    const uint32_t uPing = smem_u32(sPingH);
    const uint32_t uHead = smem_u32(sHead);
    const uint32_t uWVs  = smem_u32(sWV);
    const uint32_t uBULs = smem_u32(sBUL);
    const uint32_t uB1s  = smem_u32(sB1);
    const uint32_t uB2s  = smem_u32(sB2);
    const uint32_t uW3s  = smem_u32(sW3);

    // ldmatrix per-thread offsets (bytes): same form for A (non-trans) and B (trans)
    const uint32_t off272 = (uint32_t)(((mtx & 1) * 8 + p) * 272 + (mtx >> 1) * 16);
    const uint32_t off144 = (uint32_t)(((mtx & 1) * 8 + p) * 144 + (mtx >> 1) * 16);

    // ============ front-end: fp16 conversion staging + cp.async for fp32 bits ============
    if (t < 128) {
        if (t < 64) cpa4(uBULs + 4u * t, bul + t);
        CP_COMMIT();
        // user gather -> sActH[t][0..63] (half)
        {
            const int uid = __ldg(user_id + base + t);
            const float4* upE = (const float4*)(user_emb + (size_t)uid * 64);
            __half* dst = sActH + t * 136;
            #pragma unroll
            for (int j = 0; j < 8; j++) {
                float4 a = __ldg(upE + 2 * j), b = __ldg(upE + 2 * j + 1);
                uint4 v;
                v.x = pk(a.x, a.y); v.y = pk(a.z, a.w);
                v.z = pk(b.x, b.y); v.w = pk(b.z, b.w);
                *(uint4*)(dst + j * 8) = v;
            }
        }
        // Wul -> half [64][72]
        #pragma unroll
        for (int i = 0; i < 8; i++) {
            int idx = t + i * 128;
            int r = idx >> 4, sg = idx & 15;
            float4 w = __ldg((const float4*)(Wul + r * 64 + sg * 4));
            uint2 v; v.x = pk(w.x, w.y); v.y = pk(w.z, w.w);
            *(uint2*)(sWulH + r * 72 + sg * 4) = v;
        }
    } else {
        const int ct = t - 128;
        // cp.async: WV + b1/b2/w3 + head (fp32, no conversion)
        {
            const float* w1p = (ct < 64) ? (w_vv + ct) : (w_ev + ct - 64);
            const float* w2p = (ct < 64) ? (w_ve + ct) : (w_ee + ct - 64);
            cpa4(uWVs + 4u * ct, w1p);
            cpa4(uWVs + 4u * (128 + ct), w2p);
            cpa4(uB1s + 4u * ct, b1 + ct);
            if (ct < 64) { cpa4(uB2s + 4u * ct, b2 + ct); cpa4(uW3s + 4u * ct, W3 + ct); }
        }
        #pragma unroll
        for (int i = 0; i < 16; i++) {
            int cid = ct + i * 128;
            int s = cid >> 4, j = cid & 15;
            int iid = __ldg(item_id + base + s);
            cpa16(uHead + 4u * (s * 68 + j * 4), entity_emb + (size_t)iid * 64 + j * 4);
        }
        CP_COMMIT();
        // item gather -> sActH[ct][64..127] (half)
        {
            const int iid = __ldg(item_id + base + ct);
            const float4* ipE = (const float4*)(item_emb + (size_t)iid * 64);
            __half* dst = sActH + ct * 136 + 64;
            #pragma unroll
            for (int j = 0; j < 8; j++) {
                float4 a = __ldg(ipE + 2 * j), b = __ldg(ipE + 2 * j + 1);
                uint4 v;
                v.x = pk(a.x, a.y); v.y = pk(a.z, a.w);
                v.z = pk(b.x, b.y); v.w = pk(b.z, b.w);
                *(uint4*)(dst + j * 8) = v;
            }
        }
        // rec_target passthrough
        if (out_size >= 2 * BTOT)
            out[BTOT + base + ct] = __ldg(rec_target + base + ct);
    }
    // W1 -> half [128][136] (all threads; 64 el each)
    #pragma unroll
    for (int i = 0; i < 16; i++) {
        int idx = t + i * 256;
        int r = idx >> 5, sg = idx & 31;
        float4 w = __ldg((const float4*)(W1 + r * 128 + sg * 4));
        uint2 v; v.x = pk(w.x, w.y); v.y = pk(w.z, w.w);
        *(uint2*)(sW1H + r * 136 + sg * 4) = v;
    }
    // W2 -> half [128][72] (all threads; 32 el each)
    #pragma unroll
    for (int i = 0; i < 8; i++) {
        int idx = t + i * 256;
        int r = idx >> 4, sg = idx & 15;
        float4 w = __ldg((const float4*)(W2 + r * 64 + sg * 4));
        uint2 v; v.x = pk(w.x, w.y); v.y = pk(w.z, w.w);
        *(uint2*)(sW2H + r * 72 + sg * 4) = v;
    }

    // ============ phase 1: user MLP (warps 0-3) || cross&compress (warps 4-7) ============
    if (t < 128) {
        const int wm = wid & 1, wn = wid >> 1;    // rows wm*64, cols wn*32
        CP_WAIT(0);                               // bul landed
        BAR_U();
        sOut[t] = 0.f;
        const uint32_t bWulB = uWuls + (uint32_t)(wn * 32 * 2) + off144;
        #pragma unroll 1
        for (int layer = 0; layer < 2; layer++) {
            float acc[4][4][4];
            #pragma unroll
            for (int mt = 0; mt < 4; mt++)
                #pragma unroll
                for (int nt = 0; nt < 4; nt++)
                    #pragma unroll
                    for (int i = 0; i < 4; i++) acc[mt][nt][i] = 0.f;
            #pragma unroll
            for (int k16 = 0; k16 < 4; k16++) {
                uint32_t a[4][4], bt0[4], bt1[4];
                #pragma unroll
                for (int mt = 0; mt < 4; mt++) {
                    uint32_t ad = layer
                        ? (uPing + (uint32_t)((wm * 64 + mt * 16) * 144 + k16 * 32) + off144)
                        : (uAct  + (uint32_t)((wm * 64 + mt * 16) * 272 + k16 * 32) + off272);
                    ldsm4(a[mt], ad);
                }
                ldsm4t(bt0, bWulB + (uint32_t)(k16 * 16 * 144));
                ldsm4t(bt1, bWulB + (uint32_t)(k16 * 16 * 144 + 32));
                #pragma unroll
                for (int mt = 0; mt < 4; mt++) {
                    mma16(acc[mt][0], a[mt], bt0);
                    mma16(acc[mt][1], a[mt], bt0 + 2);
                    mma16(acc[mt][2], a[mt], bt1);
                    mma16(acc[mt][3], a[mt], bt1 + 2);
                }
            }
            const int r0b = wm * 64 + (l >> 2);
            const int cb  = wn * 32 + 2 * (l & 3);
            #pragma unroll
            for (int mt = 0; mt < 4; mt++)
                #pragma unroll
                for (int nt = 0; nt < 4; nt++) {
                    int c = cb + nt * 8;
                    float bb0 = sBUL[c], bb1 = sBUL[c + 1];
                    int r0 = r0b + mt * 16;
                    uint32_t v0 = pk(fmaxf(acc[mt][nt][0] + bb0, 0.f),
                                     fmaxf(acc[mt][nt][1] + bb1, 0.f));
                    uint32_t v1 = pk(fmaxf(acc[mt][nt][2] + bb0, 0.f),
                                     fmaxf(acc[mt][nt][3] + bb1, 0.f));
                    if (layer == 0) {
                        *(uint32_t*)(sPingH + r0 * 72 + c) = v0;
                        *(uint32_t*)(sPingH + (r0 + 8) * 72 + c) = v1;
                    } else {
                        *(uint32_t*)(sActH + r0 * 136 + c) = v0;
                        *(uint32_t*)(sActH + (r0 + 8) * 136 + c) = v1;
                    }
                }
            if (layer == 0) BAR_U();   // ping visible before layer-2 reads
        }
    } else {
        const int s = t - 128;                    // 1 thread per sample
        const float bvv = __ldg(b_v), bee = __ldg(b_e);
        CP_WAIT(0);                               // head + WV + smalls landed
        BAR_C();
        __half* itp = sActH + s * 136 + 64;
        float*  hdp = sHead + s * 68;
        #pragma unroll 1
        for (int layer = 0; layer < 2; layer++) {
            float s1 = 0.f, s2 = 0.f, s3 = 0.f, s4 = 0.f;
            #pragma unroll
            for (int j = 0; j < 8; j++) {
                uint4 raw = *(const uint4*)(itp + j * 8);
                float2 i0 = up(raw.x), i1 = up(raw.y), i2 = up(raw.z), i3 = up(raw.w);
                float4 hA = *(const float4*)&hdp[j * 8];
                float4 hB = *(const float4*)&hdp[j * 8 + 4];
                float4 wvA = *(const float4*)&sWV[j * 8];
                float4 wvB = *(const float4*)&sWV[j * 8 + 4];
                float4 weA = *(const float4*)&sWV[64 + j * 8];
                float4 weB = *(const float4*)&sWV[64 + j * 8 + 4];
                s1 = fmaf(hA.x, wvA.x, fmaf(hA.y, wvA.y, fmaf(hA.z, wvA.z, fmaf(hA.w, wvA.w, s1))));
                s1 = fmaf(hB.x, wvB.x, fmaf(hB.y, wvB.y, fmaf(hB.z, wvB.z, fmaf(hB.w, wvB.w, s1))));
                s2 = fmaf(i0.x, weA.x, fmaf(i0.y, weA.y, fmaf(i1.x, weA.z, fmaf(i1.y, weA.w, s2))));
                s2 = fmaf(i2.x, weB.x, fmaf(i2.y, weB.y, fmaf(i3.x, weB.z, fmaf(i3.y, weB.w, s2))));
                if (layer == 0) {
                    float4 wfA = *(const float4*)&sWV[128 + j * 8];
                    float4 wfB = *(const float4*)&sWV[128 + j * 8 + 4];
                    float4 wgA = *(const float4*)&sWV[192 + j * 8];
                    float4 wgB = *(const float4*)&sWV[192 + j * 8 + 4];
                    s3 = fmaf(hA.x, wfA.x, fmaf(hA.y, wfA.y, fmaf(hA.z, wfA.z, fmaf(hA.w, wfA.w, s3))));
                    s3 = fmaf(hB.x, wfB.x, fmaf(hB.y, wfB.y, fmaf(hB.z, wfB.z, fmaf(hB.w, wfB.w, s3))));
                    s4 = fmaf(i0.x, wgA.x, fmaf(i0.y, wgA.y, fmaf(i1.x, wgA.z, fmaf(i1.y, wgA.w, s4))));
                    s4 = fmaf(i2.x, wgB.x, fmaf(i2.y, wgB.y, fmaf(i3.x, wgB.z, fmaf(i3.y, wgB.w, s4))));
                }
            }
            #pragma unroll
            for (int j = 0; j < 8; j++) {
                uint4 raw = *(const uint4*)(itp + j * 8);
                float2 i0 = up(raw.x), i1 = up(raw.y), i2 = up(raw.z), i3 = up(raw.w);
                float4 hA = *(const float4*)&hdp[j * 8];
                float4 hB = *(const float4*)&hdp[j * 8 + 4];
                uint4 nv;
                nv.x = pk(fmaf(i0.x, s1, fmaf(hA.x, s2, bvv)), fmaf(i0.y, s1, fmaf(hA.y, s2, bvv)));
                nv.y = pk(fmaf(i1.x, s1, fmaf(hA.z, s2, bvv)), fmaf(i1.y, s1, fmaf(hA.w, s2, bvv)));
                nv.z = pk(fmaf(i2.x, s1, fmaf(hB.x, s2, bvv)), fmaf(i2.y, s1, fmaf(hB.y, s2, bvv)));
                nv.w = pk(fmaf(i3.x, s1, fmaf(hB.z, s2, bvv)), fmaf(i3.y, s1, fmaf(hB.w, s2, bvv)));
                *(uint4*)(itp + j * 8) = nv;
                if (layer == 0) {     // head update dead after last layer
                    float4 nA, nB;
                    nA.x = fmaf(i0.x, s3, fmaf(hA.x, s4, bee));
                    nA.y = fmaf(i0.y, s3, fmaf(hA.y, s4, bee));
                    nA.z = fmaf(i1.x, s3, fmaf(hA.z, s4, bee));
                    nA.w = fmaf(i1.y, s3, fmaf(hA.w, s4, bee));
                    nB.x = fmaf(i2.x, s3, fmaf(hB.x, s4, bee));
                    nB.y = fmaf(i2.y, s3, fmaf(hB.y, s4, bee));
                    nB.z = fmaf(i3.x, s3, fmaf(hB.z, s4, bee));
                    nB.w = fmaf(i3.y, s3, fmaf(hB.w, s4, bee));
                    *(float4*)&hdp[j * 8] = nA;
                    *(float4*)&hdp[j * 8 + 4] = nB;
                }
            }
        }
    }

    __syncthreads();     // concat: user cols + item cols + W1 + W2 visible block-wide

    // ============ GEMM1: row-grouped; group g2 owns rows g2*64..+63; warps 4N ============
    const int g2 = wid >> 2, w4 = wid & 3;
    {
        float acc[4][4][4];
        #pragma unroll
        for (int mt = 0; mt < 4; mt++)
            #pragma unroll
            for (int nt = 0; nt < 4; nt++)
                #pragma unroll
                for (int i = 0; i < 4; i++) acc[mt][nt][i] = 0.f;
        const uint32_t bW1B = uW1s + (uint32_t)(w4 * 32 * 2) + off272;
        #pragma unroll
        for (int k16 = 0; k16 < 8; k16++) {
            uint32_t a[4][4], bt0[4], bt1[4];
            #pragma unroll
            for (int mt = 0; mt < 4; mt++)
                ldsm4(a[mt], uAct + (uint32_t)((g2 * 64 + mt * 16) * 272 + k16 * 32) + off272);
            ldsm4t(bt0, bW1B + (uint32_t)(k16 * 16 * 272));
            ldsm4t(bt1, bW1B + (uint32_t)(k16 * 16 * 272 + 32));
            #pragma unroll
            for (int mt = 0; mt < 4; mt++) {
                mma16(acc[mt][0], a[mt], bt0);
                mma16(acc[mt][1], a[mt], bt0 + 2);
                mma16(acc[mt][2], a[mt], bt1);
                mma16(acc[mt][3], a[mt], bt1 + 2);
            }
        }
        BAR_G(g2);          // group's reads done before h1 overwrites its rows
        const int r0b = g2 * 64 + (l >> 2);
        const int cb  = w4 * 32 + 2 * (l & 3);
        #pragma unroll
        for (int mt = 0; mt < 4; mt++)
            #pragma unroll
            for (int nt = 0; nt < 4; nt++) {
                int c = cb + nt * 8;
                float bb0 = sB1[c], bb1 = sB1[c + 1];
                int r0 = r0b + mt * 16;
                *(uint32_t*)(sActH + r0 * 136 + c) =
                    pk(fmaxf(acc[mt][nt][0] + bb0, 0.f), fmaxf(acc[mt][nt][1] + bb1, 0.f));
                *(uint32_t*)(sActH + (r0 + 8) * 136 + c) =
                    pk(fmaxf(acc[mt][nt][2] + bb0, 0.f), fmaxf(acc[mt][nt][3] + bb1, 0.f));
            }
    }
    BAR_G(g2);           // group's h1 rows visible

    // ============ GEMM2: per group rows 64; warps 2M x 2N (32x32); fused 64->1 ============
    {
        const int mh = w4 & 1, nh = w4 >> 1;
        float acc[2][4][4];
        #pragma unroll
        for (int mt = 0; mt < 2; mt++)
            #pragma unroll
            for (int nt = 0; nt < 4; nt++)
                #pragma unroll
                for (int i = 0; i < 4; i++) acc[mt][nt][i] = 0.f;
        const int rowb = g2 * 64 + mh * 32;
        const uint32_t bW2B = uW2s + (uint32_t)(nh * 32 * 2) + off144;
        #pragma unroll
        for (int k16 = 0; k16 < 8; k16++) {
            uint32_t a[2][4], bt0[4], bt1[4];
            #pragma unroll
            for (int mt = 0; mt < 2; mt++)
                ldsm4(a[mt], uAct + (uint32_t)((rowb + mt * 16) * 272 + k16 * 32) + off272);
            ldsm4t(bt0, bW2B + (uint32_t)(k16 * 16 * 144));
            ldsm4t(bt1, bW2B + (uint32_t)(k16 * 16 * 144 + 32));
            #pragma unroll
            for (int mt = 0; mt < 2; mt++) {
                mma16(acc[mt][0], a[mt], bt0);
                mma16(acc[mt][1], a[mt], bt0 + 2);
                mma16(acc[mt][2], a[mt], bt1);
                mma16(acc[mt][3], a[mt], bt1 + 2);
            }
        }
        // fused: p[row] += relu(h2+b2)*w3; shfl-reduce over 4-lane col group; atomic sOut
        const int cb = nh * 32 + 2 * (l & 3);
        float part[2][2];
        part[0][0] = part[0][1] = part[1][0] = part[1][1] = 0.f;
        #pragma unroll
        for (int nt = 0; nt < 4; nt++) {
            int c = cb + nt * 8;
            float bb0 = sB2[c], bb1 = sB2[c + 1];
            float w30 = sW3[c], w31 = sW3[c + 1];
            #pragma unroll
            for (int mt = 0; mt < 2; mt++) {
                part[mt][0] = fmaf(fmaxf(acc[mt][nt][0] + bb0, 0.f), w30,
                              fmaf(fmaxf(acc[mt][nt][1] + bb1, 0.f), w31, part[mt][0]));
                part[mt][1] = fmaf(fmaxf(acc[mt][nt][2] + bb0, 0.f), w30,
                              fmaf(fmaxf(acc[mt][nt][3] + bb1, 0.f), w31, part[mt][1]));
            }
        }
        #pragma unroll
        for (int mt = 0; mt < 2; mt++)
            #pragma unroll
            for (int rh = 0; rh < 2; rh++) {
                part[mt][rh] += __shfl_xor_sync(0xffffffffu, part[mt][rh], 1);
                part[mt][rh] += __shfl_xor_sync(0xffffffffu, part[mt][rh], 2);
            }
        if ((l & 3) == 0) {
            const int r0b = rowb + (l >> 2);
            #pragma unroll
            for (int mt = 0; mt < 2; mt++) {
                atomicAdd(&sOut[r0b + mt * 16],     part[mt][0]);
                atomicAdd(&sOut[r0b + mt * 16 + 8], part[mt][1]);
            }
        }
    }
    BAR_G(g2);           // group's sOut rows complete

    // ============ output (group-local rows) ============
    {
        const int gt = t & 127;
        if (gt < 64) {
            const int r = g2 * 64 + gt;
            out[base + r] = fmaxf(sOut[r] + __ldg(b3), 0.f);
        }
    }
}

extern "C" void kernel_launch(void* const* d_in, const int* in_sizes, int n_in,
                              void* d_out, int out_size)
{
    const int*   user_id    = (const int*)d_in[0];
    const int*   item_id    = (const int*)d_in[1];
    const float* rec_target = (const float*)d_in[2];
    const float* user_emb   = (const float*)d_in[3];
    const float* item_emb   = (const float*)d_in[4];
    const float* entity_emb = (const float*)d_in[5];
    const float* w_vv = (const float*)d_in[6];
    const float* w_ev = (const float*)d_in[7];
    const float* w_ve = (const float*)d_in[8];
    const float* w_ee = (const float*)d_in[9];
    const float* b_v  = (const float*)d_in[10];
    const float* b_e  = (const float*)d_in[11];
    const float* Wul  = (const float*)d_in[12];
    const float* bul  = (const float*)d_in[13];
    const float* W1   = (const float*)d_in[14];
    const float* b1   = (const float*)d_in[15];
    const float* W2   = (const float*)d_in[16];
    const float* b2   = (const float*)d_in[17];
    const float* W3   = (const float*)d_in[18];
    const float* b3   = (const float*)d_in[19];

    cudaFuncSetAttribute(multikr_mma_kernel,
                         cudaFuncAttributeMaxDynamicSharedMemorySize, SMEM_BYTES);

    const int n = in_sizes[0];      // 16384
    const int nblk = n / 128;       // 128 blocks, one wave
    multikr_mma_kernel<<<nblk, NT, SMEM_BYTES>>>(
        user_id, item_id, rec_target, user_emb, item_emb, entity_emb,
        w_vv, w_ev, w_ve, w_ee, b_v, b_e, Wul, bul,
        W1, b1, W2, b2, W3, b3,
        (float*)d_out, out_size);
}

// round 16
// speedup vs baseline: 1.0131x; 1.0131x over previous
#include <cuda_runtime.h>
#include <cuda_fp16.h>
#include <cstdint>

#define NT 256
#define SAMP 64
#define BTOT 16384

// ---- dynamic smem layout (BYTE offsets), per CTA = 109056 B -> 2 CTAs/SM ----
#define B_ACT   0          // half [64][136]  (272B/row)
#define B_W1    17408      // half [128][136] = 34816
#define B_WUL   52224      // half [64][72]   = 9216
#define B_W2    61440      // half [128][72]  = 18432
#define B_PING  79872      // half [64][72]   = 9216
#define B_HEAD  89088      // float [64][68]  = 17408
#define B_WV    106496     // float[256]
#define B_BUL   107520     // float[64]
#define B_B1    107776     // float[128]
#define B_B2    108288     // float[64]
#define B_W3    108544     // float[64]
#define B_OUT   108800     // float[64]
#define SMEM_BYTES 109056

__device__ __forceinline__ uint32_t smem_u32(const void* p) {
    uint32_t a;
    asm("{ .reg .u64 t; cvta.to.shared.u64 t, %1; cvt.u32.u64 %0, t; }" : "=r"(a) : "l"(p));
    return a;
}
__device__ __forceinline__ uint32_t pk(float a, float b) {
    __half2 h = __floats2half2_rn(a, b);
    return *(uint32_t*)&h;
}
__device__ __forceinline__ float2 up(uint32_t u) {
    return __half22float2(*(__half2*)&u);
}
__device__ __forceinline__ void ldsm4(uint32_t* r, uint32_t addr) {
    asm volatile("ldmatrix.sync.aligned.m8n8.x4.shared.b16 {%0,%1,%2,%3}, [%4];"
                 : "=r"(r[0]), "=r"(r[1]), "=r"(r[2]), "=r"(r[3]) : "r"(addr));
}
__device__ __forceinline__ void ldsm4t(uint32_t* r, uint32_t addr) {
    asm volatile("ldmatrix.sync.aligned.m8n8.x4.trans.shared.b16 {%0,%1,%2,%3}, [%4];"
                 : "=r"(r[0]), "=r"(r[1]), "=r"(r[2]), "=r"(r[3]) : "r"(addr));
}
__device__ __forceinline__ void mma16(float* c, const uint32_t* a, const uint32_t* b) {
    asm("mma.sync.aligned.m16n8k16.row.col.f32.f16.f16.f32 "
        "{%0,%1,%2,%3},{%4,%5,%6,%7},{%8,%9},{%0,%1,%2,%3};"
        : "+f"(c[0]), "+f"(c[1]), "+f"(c[2]), "+f"(c[3])
        : "r"(a[0]), "r"(a[1]), "r"(a[2]), "r"(a[3]), "r"(b[0]), "r"(b[1]));
}
__device__ __forceinline__ void cpa16(uint32_t dst, const void* src) {
    asm volatile("cp.async.cg.shared.global [%0], [%1], 16;" :: "r"(dst), "l"(src));
}
__device__ __forceinline__ void cpa4(uint32_t dst, const void* src) {
    asm volatile("cp.async.ca.shared.global [%0], [%1], 4;" :: "r"(dst), "l"(src));
}
#define CP_COMMIT() asm volatile("cp.async.commit_group;" ::: "memory")
#define CP_WAIT(n)  asm volatile("cp.async.wait_group %0;" :: "n"(n) : "memory")
#define BAR_U() asm volatile("bar.sync 1, 128;" ::: "memory")
#define BAR_C() asm volatile("bar.sync 2, 128;" ::: "memory")

__global__ __launch_bounds__(NT, 2)
void multikr_mma_kernel(const int* __restrict__ user_id,
                        const int* __restrict__ item_id,
                        const float* __restrict__ rec_target,
                        const float* __restrict__ user_emb,
                        const float* __restrict__ item_emb,
                        const float* __restrict__ entity_emb,
                        const float* __restrict__ w_vv,
                        const float* __restrict__ w_ev,
                        const float* __restrict__ w_ve,
                        const float* __restrict__ w_ee,
                        const float* __restrict__ b_v,
                        const float* __restrict__ b_e,
                        const float* __restrict__ Wul,
                        const float* __restrict__ bul,
                        const float* __restrict__ W1,
                        const float* __restrict__ b1,
                        const float* __restrict__ W2,
                        const float* __restrict__ b2,
                        const float* __restrict__ W3,
                        const float* __restrict__ b3,
                        float* __restrict__ out,
                        int out_size)
{
    extern __shared__ char smem[];
    __half* sActH  = (__half*)(smem + B_ACT);
    __half* sW1H   = (__half*)(smem + B_W1);
    __half* sWulH  = (__half*)(smem + B_WUL);
    __half* sW2H   = (__half*)(smem + B_W2);
    __half* sPingH = (__half*)(smem + B_PING);
    float*  sHead  = (float*)(smem + B_HEAD);
    float*  sWV    = (float*)(smem + B_WV);
    float*  sBUL   = (float*)(smem + B_BUL);
    float*  sB1    = (float*)(smem + B_B1);
    float*  sB2    = (float*)(smem + B_B2);
    float*  sW3    = (float*)(smem + B_W3);
    float*  sOut   = (float*)(smem + B_OUT);

    const int t    = threadIdx.x;
    const int l    = t & 31;
    const int wid  = t >> 5;
    const int mtx  = l >> 3, p = l & 7;
    const int base = blockIdx.x * SAMP;

    const uint32_t uAct  = smem_u32(sActH);
    const uint32_t uW1s  = smem_u32(sW1H);
    const uint32_t uWuls = smem_u32(sWulH);
    const uint32_t uW2s  = smem_u32(sW2H);
    const uint32_t uPing = smem_u32(sPingH);
    const uint32_t uHead = smem_u32(sHead);
    const uint32_t uWVs  = smem_u32(sWV);
    const uint32_t uBULs = smem_u32(sBUL);
    const uint32_t uB1s  = smem_u32(sB1);
    const uint32_t uB2s  = smem_u32(sB2);
    const uint32_t uW3s  = smem_u32(sW3);

    // ldmatrix per-thread offsets (bytes) — same form for A (non-trans) and trans-B
    const uint32_t off272 = (uint32_t)(((mtx & 1) * 8 + p) * 272 + (mtx >> 1) * 16);
    const uint32_t off144 = (uint32_t)(((mtx & 1) * 8 + p) * 144 + (mtx >> 1) * 16);

    // ============ front-end ============
    if (t < 128) {
        if (t < 64) cpa4(uBULs + 4u * t, bul + t);
        CP_COMMIT();
        // user gather (64 samples x 16 segs / 128 thr = 8 units) -> fp16 sActH cols 0-63
        #pragma unroll
        for (int i = 0; i < 8; i++) {
            int cid = t + i * 128;
            int s = cid >> 4, j = cid & 15;
            int uid = __ldg(user_id + base + s);
            float4 w = __ldg((const float4*)(user_emb + (size_t)uid * 64 + j * 4));
            uint2 v; v.x = pk(w.x, w.y); v.y = pk(w.z, w.w);
            *(uint2*)(sActH + s * 136 + j * 4) = v;
        }
        // Wul -> half [64][72]
        #pragma unroll
        for (int i = 0; i < 8; i++) {
            int idx = t + i * 128;
            int r = idx >> 4, sg = idx & 15;
            float4 w = __ldg((const float4*)(Wul + r * 64 + sg * 4));
            uint2 v; v.x = pk(w.x, w.y); v.y = pk(w.z, w.w);
            *(uint2*)(sWulH + r * 72 + sg * 4) = v;
        }
    } else {
        const int ct = t - 128;
        // WV + b1/b2/w3 + head via cp.async
        {
            const float* w1p = (ct < 64) ? (w_vv + ct) : (w_ev + ct - 64);
            const float* w2p = (ct < 64) ? (w_ve + ct) : (w_ee + ct - 64);
            cpa4(uWVs + 4u * ct, w1p);
            cpa4(uWVs + 4u * (128 + ct), w2p);
            cpa4(uB1s + 4u * ct, b1 + ct);
            if (ct < 64) { cpa4(uB2s + 4u * ct, b2 + ct); cpa4(uW3s + 4u * ct, W3 + ct); }
        }
        #pragma unroll
        for (int i = 0; i < 8; i++) {
            int cid = ct + i * 128;
            int s = cid >> 4, j = cid & 15;
            int iid = __ldg(item_id + base + s);
            cpa16(uHead + 4u * (s * 68 + j * 4), entity_emb + (size_t)iid * 64 + j * 4);
        }
        CP_COMMIT();
        // item gather -> fp16 sActH cols 64-127
        #pragma unroll
        for (int i = 0; i < 8; i++) {
            int cid = ct + i * 128;
            int s = cid >> 4, j = cid & 15;
            int iid = __ldg(item_id + base + s);
            float4 w = __ldg((const float4*)(item_emb + (size_t)iid * 64 + j * 4));
            uint2 v; v.x = pk(w.x, w.y); v.y = pk(w.z, w.w);
            *(uint2*)(sActH + s * 136 + 64 + j * 4) = v;
        }
        // rec_target passthrough
        if (ct < 64 && out_size >= 2 * BTOT)
            out[BTOT + base + ct] = __ldg(rec_target + base + ct);
    }
    // W1 -> half [128][136] (all threads, 16 f4 units each)
    #pragma unroll
    for (int i = 0; i < 16; i++) {
        int idx = t + i * 256;
        int r = idx >> 5, sg = idx & 31;
        float4 w = __ldg((const float4*)(W1 + r * 128 + sg * 4));
        uint2 v; v.x = pk(w.x, w.y); v.y = pk(w.z, w.w);
        *(uint2*)(sW1H + r * 136 + sg * 4) = v;
    }
    // W2 -> half [128][72] (all threads, 8 f4 units each)
    #pragma unroll
    for (int i = 0; i < 8; i++) {
        int idx = t + i * 256;
        int r = idx >> 4, sg = idx & 15;
        float4 w = __ldg((const float4*)(W2 + r * 64 + sg * 4));
        uint2 v; v.x = pk(w.x, w.y); v.y = pk(w.z, w.w);
        *(uint2*)(sW2H + r * 72 + sg * 4) = v;
    }

    // ============ phase 1: user MLP (warps 0-3) || cross&compress (warps 4-7) ============
    if (t < 128) {
        const int wn = wid;                       // N sixteenth: cols wn*16
        CP_WAIT(0);
        BAR_U();                                  // gathers + Wul + bul visible to user half
        if (t < 64) sOut[t] = 0.f;
        const uint32_t bWulB = uWuls + (uint32_t)(wn * 16 * 2) + off144;
        #pragma unroll 1
        for (int layer = 0; layer < 2; layer++) {
            float acc[4][2][4];
            #pragma unroll
            for (int mt = 0; mt < 4; mt++)
                #pragma unroll
                for (int nt = 0; nt < 2; nt++)
                    #pragma unroll
                    for (int i = 0; i < 4; i++) acc[mt][nt][i] = 0.f;
            #pragma unroll
            for (int k16 = 0; k16 < 4; k16++) {
                uint32_t a[4][4], bt[4];
                #pragma unroll
                for (int mt = 0; mt < 4; mt++) {
                    uint32_t ad = layer
                        ? (uPing + (uint32_t)(mt * 16 * 144 + k16 * 32) + off144)
                        : (uAct  + (uint32_t)(mt * 16 * 272 + k16 * 32) + off272);
                    ldsm4(a[mt], ad);
                }
                ldsm4t(bt, bWulB + (uint32_t)(k16 * 16 * 144));
                #pragma unroll
                for (int mt = 0; mt < 4; mt++) {
                    mma16(acc[mt][0], a[mt], bt);
                    mma16(acc[mt][1], a[mt], bt + 2);
                }
            }
            const int r0b = l >> 2;
            const int cb  = wn * 16 + 2 * (l & 3);
            #pragma unroll
            for (int mt = 0; mt < 4; mt++)
                #pragma unroll
                for (int nt = 0; nt < 2; nt++) {
                    int c = cb + nt * 8;
                    float bb0 = sBUL[c], bb1 = sBUL[c + 1];
                    int r0 = r0b + mt * 16;
                    uint32_t v0 = pk(fmaxf(acc[mt][nt][0] + bb0, 0.f),
                                     fmaxf(acc[mt][nt][1] + bb1, 0.f));
                    uint32_t v1 = pk(fmaxf(acc[mt][nt][2] + bb0, 0.f),
                                     fmaxf(acc[mt][nt][3] + bb1, 0.f));
                    if (layer == 0) {
                        *(uint32_t*)(sPingH + r0 * 72 + c) = v0;
                        *(uint32_t*)(sPingH + (r0 + 8) * 72 + c) = v1;
                    } else {
                        *(uint32_t*)(sActH + r0 * 136 + c) = v0;
                        *(uint32_t*)(sActH + (r0 + 8) * 136 + c) = v1;
                    }
                }
            if (layer == 0) BAR_U();   // ping visible before layer-2 reads
        }
    } else {
        const int tc = t - 128;                   // 2 threads per sample
        const int s  = tc >> 1, kh = tc & 1;
        const float bvv = __ldg(b_v), bee = __ldg(b_e);
        CP_WAIT(0);                               // head + WV + smalls landed
        BAR_C();                                  // + item fp16 visible across cross half
        __half* itp = sActH + s * 136 + 64 + kh * 32;
        float*  hdp = sHead + s * 68 + kh * 32;
        const float* wv0 = sWV + kh * 32;
        #pragma unroll 1
        for (int layer = 0; layer < 2; layer++) {
            float s1 = 0.f, s2 = 0.f, s3 = 0.f, s4 = 0.f;
            #pragma unroll
            for (int j = 0; j < 4; j++) {
                uint4 raw = *(const uint4*)(itp + j * 8);
                float2 i0 = up(raw.x), i1 = up(raw.y), i2 = up(raw.z), i3 = up(raw.w);
                float4 hA = *(const float4*)&hdp[j * 8];
                float4 hB = *(const float4*)&hdp[j * 8 + 4];
                float4 wvA = *(const float4*)&wv0[j * 8];
                float4 wvB = *(const float4*)&wv0[j * 8 + 4];
                float4 weA = *(const float4*)&wv0[64 + j * 8];
                float4 weB = *(const float4*)&wv0[64 + j * 8 + 4];
                s1 = fmaf(hA.x, wvA.x, fmaf(hA.y, wvA.y, fmaf(hA.z, wvA.z, fmaf(hA.w, wvA.w, s1))));
                s1 = fmaf(hB.x, wvB.x, fmaf(hB.y, wvB.y, fmaf(hB.z, wvB.z, fmaf(hB.w, wvB.w, s1))));
                s2 = fmaf(i0.x, weA.x, fmaf(i0.y, weA.y, fmaf(i1.x, weA.z, fmaf(i1.y, weA.w, s2))));
                s2 = fmaf(i2.x, weB.x, fmaf(i2.y, weB.y, fmaf(i3.x, weB.z, fmaf(i3.y, weB.w, s2))));
                if (layer == 0) {
                    float4 wfA = *(const float4*)&wv0[128 + j * 8];
                    float4 wfB = *(const float4*)&wv0[128 + j * 8 + 4];
                    float4 wgA = *(const float4*)&wv0[192 + j * 8];
                    float4 wgB = *(const float4*)&wv0[192 + j * 8 + 4];
                    s3 = fmaf(hA.x, wfA.x, fmaf(hA.y, wfA.y, fmaf(hA.z, wfA.z, fmaf(hA.w, wfA.w, s3))));
                    s3 = fmaf(hB.x, wfB.x, fmaf(hB.y, wfB.y, fmaf(hB.z, wfB.z, fmaf(hB.w, wfB.w, s3))));
                    s4 = fmaf(i0.x, wgA.x, fmaf(i0.y, wgA.y, fmaf(i1.x, wgA.z, fmaf(i1.y, wgA.w, s4))));
                    s4 = fmaf(i2.x, wgB.x, fmaf(i2.y, wgB.y, fmaf(i3.x, wgB.z, fmaf(i3.y, wgB.w, s4))));
                }
            }
            s1 += __shfl_xor_sync(0xffffffffu, s1, 1);
            s2 += __shfl_xor_sync(0xffffffffu, s2, 1);
            if (layer == 0) {
                s3 += __shfl_xor_sync(0xffffffffu, s3, 1);
                s4 += __shfl_xor_sync(0xffffffffu, s4, 1);
            }
            #pragma unroll
            for (int j = 0; j < 4; j++) {
                uint4 raw = *(const uint4*)(itp + j * 8);
                float2 i0 = up(raw.x), i1 = up(raw.y), i2 = up(raw.z), i3 = up(raw.w);
                float4 hA = *(const float4*)&hdp[j * 8];
                float4 hB = *(const float4*)&hdp[j * 8 + 4];
                uint4 nv;
                nv.x = pk(fmaf(i0.x, s1, fmaf(hA.x, s2, bvv)), fmaf(i0.y, s1, fmaf(hA.y, s2, bvv)));
                nv.y = pk(fmaf(i1.x, s1, fmaf(hA.z, s2, bvv)), fmaf(i1.y, s1, fmaf(hA.w, s2, bvv)));
                nv.z = pk(fmaf(i2.x, s1, fmaf(hB.x, s2, bvv)), fmaf(i2.y, s1, fmaf(hB.y, s2, bvv)));
                nv.w = pk(fmaf(i3.x, s1, fmaf(hB.z, s2, bvv)), fmaf(i3.y, s1, fmaf(hB.w, s2, bvv)));
                *(uint4*)(itp + j * 8) = nv;
                if (layer == 0) {     // head update dead after last layer
                    float4 nA, nB;
                    nA.x = fmaf(i0.x, s3, fmaf(hA.x, s4, bee));
                    nA.y = fmaf(i0.y, s3, fmaf(hA.y, s4, bee));
                    nA.z = fmaf(i1.x, s3, fmaf(hA.z, s4, bee));
                    nA.w = fmaf(i1.y, s3, fmaf(hA.w, s4, bee));
                    nB.x = fmaf(i2.x, s3, fmaf(hB.x, s4, bee));
                    nB.y = fmaf(i2.y, s3, fmaf(hB.y, s4, bee));
                    nB.z = fmaf(i3.x, s3, fmaf(hB.z, s4, bee));
                    nB.w = fmaf(i3.y, s3, fmaf(hB.w, s4, bee));
                    *(float4*)&hdp[j * 8] = nA;
                    *(float4*)&hdp[j * 8 + 4] = nB;
                }
            }
        }
    }

    __syncthreads();     // concat: user cols + item cols + W1 + W2 visible block-wide

    // ============ GEMM1: M=64, N=128; 8 warps = 2M x 4N ============
    {
        const int wmg = wid & 1, wng = wid >> 1;  // rows wmg*32, cols wng*32
        float acc[2][4][4];
        #pragma unroll
        for (int mt = 0; mt < 2; mt++)
            #pragma unroll
            for (int nt = 0; nt < 4; nt++)
                #pragma unroll
                for (int i = 0; i < 4; i++) acc[mt][nt][i] = 0.f;
        const uint32_t bW1B = uW1s + (uint32_t)(wng * 32 * 2) + off272;
        #pragma unroll
        for (int k16 = 0; k16 < 8; k16++) {
            uint32_t a[2][4], bt0[4], bt1[4];
            #pragma unroll
            for (int mt = 0; mt < 2; mt++)
                ldsm4(a[mt], uAct + (uint32_t)((wmg * 32 + mt * 16) * 272 + k16 * 32) + off272);
            ldsm4t(bt0, bW1B + (uint32_t)(k16 * 16 * 272));
            ldsm4t(bt1, bW1B + (uint32_t)(k16 * 16 * 272 + 32));
            #pragma unroll
            for (int mt = 0; mt < 2; mt++) {
                mma16(acc[mt][0], a[mt], bt0);
                mma16(acc[mt][1], a[mt], bt0 + 2);
                mma16(acc[mt][2], a[mt], bt1);
                mma16(acc[mt][3], a[mt], bt1 + 2);
            }
        }
        __syncthreads();    // all GEMM1 reads done before h1 overwrites sActH
        const int r0b = wmg * 32 + (l >> 2);
        const int cb  = wng * 32 + 2 * (l & 3);
        #pragma unroll
        for (int mt = 0; mt < 2; mt++)
            #pragma unroll
            for (int nt = 0; nt < 4; nt++) {
                int c = cb + nt * 8;
                float bb0 = sB1[c], bb1 = sB1[c + 1];
                int r0 = r0b + mt * 16;
                *(uint32_t*)(sActH + r0 * 136 + c) =
                    pk(fmaxf(acc[mt][nt][0] + bb0, 0.f), fmaxf(acc[mt][nt][1] + bb1, 0.f));
                *(uint32_t*)(sActH + (r0 + 8) * 136 + c) =
                    pk(fmaxf(acc[mt][nt][2] + bb0, 0.f), fmaxf(acc[mt][nt][3] + bb1, 0.f));
            }
    }
    __syncthreads();     // h1 visible

    // ============ GEMM2: M=64, N=64; 8 warps = 4M x 2N (16x32) + fused 64->1 ============
    {
        const int mb = wid & 3, nh = wid >> 2;    // rows mb*16, cols nh*32
        float acc[4][4];
        #pragma unroll
        for (int nt = 0; nt < 4; nt++)
            #pragma unroll
            for (int i = 0; i < 4; i++) acc[nt][i] = 0.f;
        const uint32_t bW2B = uW2s + (uint32_t)(nh * 32 * 2) + off144;
        #pragma unroll
        for (int k16 = 0; k16 < 8; k16++) {
            uint32_t a[4], bt0[4], bt1[4];
            ldsm4(a, uAct + (uint32_t)(mb * 16 * 272 + k16 * 32) + off272);
            ldsm4t(bt0, bW2B + (uint32_t)(k16 * 16 * 144));
            ldsm4t(bt1, bW2B + (uint32_t)(k16 * 16 * 144 + 32));
            mma16(acc[0], a, bt0);
            mma16(acc[1], a, bt0 + 2);
            mma16(acc[2], a, bt1);
            mma16(acc[3], a, bt1 + 2);
        }
        // fused final: p[row] += relu(h2+b2)*w3; shfl-reduce over 4-lane col group
        const int cb = nh * 32 + 2 * (l & 3);
        float p0 = 0.f, p1 = 0.f;
        #pragma unroll
        for (int nt = 0; nt < 4; nt++) {
            int c = cb + nt * 8;
            float bb0 = sB2[c], bb1 = sB2[c + 1];
            float w30 = sW3[c], w31 = sW3[c + 1];
            p0 = fmaf(fmaxf(acc[nt][0] + bb0, 0.f), w30,
                 fmaf(fmaxf(acc[nt][1] + bb1, 0.f), w31, p0));
            p1 = fmaf(fmaxf(acc[nt][2] + bb0, 0.f), w30,
                 fmaf(fmaxf(acc[nt][3] + bb1, 0.f), w31, p1));
        }
        p0 += __shfl_xor_sync(0xffffffffu, p0, 1);
        p0 += __shfl_xor_sync(0xffffffffu, p0, 2);
        p1 += __shfl_xor_sync(0xffffffffu, p1, 1);
        p1 += __shfl_xor_sync(0xffffffffu, p1, 2);
        if ((l & 3) == 0) {
            const int r = mb * 16 + (l >> 2);
            atomicAdd(&sOut[r], p0);
            atomicAdd(&sOut[r + 8], p1);
        }
    }
    __syncthreads();

    // ============ output ============
    if (t < 64)
        out[base + t] = fmaxf(sOut[t] + __ldg(b3), 0.f);
}

extern "C" void kernel_launch(void* const* d_in, const int* in_sizes, int n_in,
                              void* d_out, int out_size)
{
    const int*   user_id    = (const int*)d_in[0];
    const int*   item_id    = (const int*)d_in[1];
    const float* rec_target = (const float*)d_in[2];
    const float* user_emb   = (const float*)d_in[3];
    const float* item_emb   = (const float*)d_in[4];
    const float* entity_emb = (const float*)d_in[5];
    const float* w_vv = (const float*)d_in[6];
    const float* w_ev = (const float*)d_in[7];
    const float* w_ve = (const float*)d_in[8];
    const float* w_ee = (const float*)d_in[9];
    const float* b_v  = (const float*)d_in[10];
    const float* b_e  = (const float*)d_in[11];
    const float* Wul  = (const float*)d_in[12];
    const float* bul  = (const float*)d_in[13];
    const float* W1   = (const float*)d_in[14];
    const float* b1   = (const float*)d_in[15];
    const float* W2   = (const float*)d_in[16];
    const float* b2   = (const float*)d_in[17];
    const float* W3   = (const float*)d_in[18];
    const float* b3   = (const float*)d_in[19];

    cudaFuncSetAttribute(multikr_mma_kernel,
                         cudaFuncAttributeMaxDynamicSharedMemorySize, SMEM_BYTES);

    const int n = in_sizes[0];      // 16384
    const int nblk = n / SAMP;      // 256 blocks; 2 CTAs/SM -> one wave
    multikr_mma_kernel<<<nblk, NT, SMEM_BYTES>>>(
        user_id, item_id, rec_target, user_emb, item_emb, entity_emb,
        w_vv, w_ev, w_ve, w_ee, b_v, b_e, Wul, bul,
        W1, b1, W2, b2, W3, b3,
        (float*)d_out, out_size);
}